// round 13
// baseline (speedup 1.0000x reference)
#include <cuda_runtime.h>
#include <cuda_fp16.h>
#include <cstdint>

// ============================================================================
// GlobalLSTMCell — R9: single 256x128 CTA per SM (8 MMA warps + 1 producer),
// 4-stage cp.async.bulk pipeline, merged prep kernel.
//   GEMM view: A = [x | h_prev]  (4096 x 2048)
//              Bp[n',k], n' = q*128 + gate*32 + j, hid = q*32 + j
//   D = A @ Bp^T, fused LSTM epilogue.
// ============================================================================

#define BATCH 4096
#define KDIM  2048
#define HID   1024

#define BM 256
#define BN 128
#define BK 64
#define NKT (KDIM / BK)     // 32 k-tiles
#define MT  (BATCH / BM)    // 16
#define NQ  (HID / 32)      // 32 q-blocks

#define A_TILE_HALF (BM * BK)   // 16384 halves = 32 KB
#define B_TILE_HALF (BN * BK)   // 8192 halves  = 16 KB
#define A_TILE_BYTES 32768
#define B_TILE_BYTES 16384
#define STAGE_BYTES  49152      // A + B
#define NSTAGE 4

// Scratch (__device__ globals only)
__device__ __half g_Apack[(size_t)MT * NKT * A_TILE_HALF];   // 16 MB
__device__ __half g_Bpack[(size_t)NQ * NKT * B_TILE_HALF];   // 16 MB
__device__ float  g_bias[4096];

// ============================================================================
// PTX helpers (base-target features only)
// ============================================================================
__device__ __forceinline__ uint32_t smem_u32(const void* p) {
    uint32_t a;
    asm("{ .reg .u64 t; cvta.to.shared.u64 t, %1; cvt.u32.u64 %0, t; }" : "=r"(a) : "l"(p));
    return a;
}

#define MBARRIER_INIT(addr, cnt) \
    asm volatile("mbarrier.init.shared.b64 [%0], %1;" :: "r"(addr), "r"((uint32_t)(cnt)) : "memory")

#define MBARRIER_EXPECT_TX(addr, tx) \
    asm volatile("mbarrier.arrive.expect_tx.shared.b64 _, [%0], %1;" \
                 :: "r"(addr), "r"((uint32_t)(tx)) : "memory")

#define MBARRIER_ARRIVE(addr) \
    asm volatile("mbarrier.arrive.shared.b64 _, [%0];" :: "r"(addr) : "memory")

#define MBARRIER_WAIT_PARITY(mbar_smem_addr, phase_parity) do {                        \
    uint32_t _mbar = (uint32_t)(mbar_smem_addr);                                       \
    uint32_t _parity = (uint32_t)(phase_parity);                                       \
    uint32_t _done;                                                                    \
    asm volatile("{ .reg .pred p;"                                                     \
        " mbarrier.try_wait.parity.acquire.cta.shared::cta.b64 p, [%1], %2;"           \
        " selp.b32 %0, 1, 0, p; }"                                                     \
        : "=r"(_done) : "r"(_mbar), "r"(_parity) : "memory");                          \
    if (!_done) {                                                                      \
        asm volatile("{ .reg .pred P1;"                                                \
            " WAIT_LOOP_%=:"                                                           \
            " mbarrier.try_wait.parity.acquire.cta.shared::cta.b64 P1, [%0], %1, 0x989680;" \
            " @P1 bra.uni WAIT_DONE_%=;"                                               \
            " bra.uni WAIT_LOOP_%=;"                                                   \
            " WAIT_DONE_%=: }"                                                         \
            :: "r"(_mbar), "r"(_parity) : "memory");                                   \
    }                                                                                  \
} while (0)

// 1D bulk async copy gmem -> smem with mbarrier tx completion (sm_90 base).
#define CP_BULK_G2S(dst_u32, src_ptr, bytes, mbar_u32) \
    asm volatile("cp.async.bulk.shared::cluster.global.mbarrier::complete_tx::bytes " \
                 "[%0], [%1], %2, [%3];" \
                 :: "r"(dst_u32), "l"(src_ptr), "r"((uint32_t)(bytes)), "r"(mbar_u32) : "memory")

#define LDMATRIX_X4(r0, r1, r2, r3, addr) \
    asm volatile("ldmatrix.sync.aligned.m8n8.x4.shared.b16 {%0,%1,%2,%3}, [%4];" \
                 : "=r"(r0), "=r"(r1), "=r"(r2), "=r"(r3) : "r"(addr))

__device__ __forceinline__ void mma_fp16(float* c, const uint32_t* a, const uint32_t* b) {
    asm volatile("mma.sync.aligned.m16n8k16.row.col.f32.f16.f16.f32 "
                 "{%0,%1,%2,%3}, {%4,%5,%6,%7}, {%8,%9}, {%0,%1,%2,%3};"
                 : "+f"(c[0]), "+f"(c[1]), "+f"(c[2]), "+f"(c[3])
                 : "r"(a[0]), "r"(a[1]), "r"(a[2]), "r"(a[3]), "r"(b[0]), "r"(b[1]));
}

__device__ __forceinline__ float fast_sigmoid(float x) {
    return 1.0f / (1.0f + __expf(-x));
}
__device__ __forceinline__ float fast_tanh(float x) {
    float xc = fminf(fmaxf(x, -15.0f), 15.0f);
    float e2 = __expf(2.0f * xc);
    return (e2 - 1.0f) / (e2 + 1.0f);
}

// ============================================================================
// SMEM layout: [0..64) mbarriers (4 full + 4 empty), stages at 1024.
// Epilogue reuses stage area: gate tile fp32 [256][132] + bias[128].
// ============================================================================
#define SMO_MBAR   0
#define SMO_STAGE  1024
#define SMEM_TOTAL (SMO_STAGE + NSTAGE * STAGE_BYTES)   // 197632, 1 CTA/SM
#define GS_STRIDE  132

// ============================================================================
// Merged prep kernel: flat grid covers A tiles, B tiles, bias.
//   blocks [0, 512)      : A tiles  (mt = b>>5, kt = b&31), 256 rows x 64 k
//   blocks [512, 1536)   : B tiles  (idx = b-512: q = idx>>5, kt = idx&31)
//   blocks [1536, 1552)  : bias
// ============================================================================
__global__ void prep_all_kernel(const float* __restrict__ x, const float* __restrict__ h_prev,
                                const float* __restrict__ W_ifo_x, const float* __restrict__ W_ifo_h,
                                const float* __restrict__ W_b_x,  const float* __restrict__ W_b_h,
                                const float* __restrict__ b_ifo_x, const float* __restrict__ b_ifo_h,
                                const float* __restrict__ b_b_x,  const float* __restrict__ b_b_h) {
    __shared__ float ts[64 * 33];
    int b = blockIdx.x;
    int tid = threadIdx.x;

    if (b < 512) {
        // ---- A pack: tile (mt,kt) = 256 rows x 64 cols fp16, swizzled ----
        int mt = b >> 5, kt = b & 31;
        __half* dst = g_Apack + ((size_t)mt * NKT + kt) * A_TILE_HALF;
        for (int task = tid; task < 256 * 8; task += 256) {
            int r = task >> 3, ch = task & 7;
            int m = mt * BM + r;
            int k0 = kt * BK + ch * 8;
            const float* src = (k0 < 1024) ? (x + (size_t)m * 1024 + k0)
                                           : (h_prev + (size_t)m * 1024 + (k0 - 1024));
            float4 v0 = *(const float4*)(src);
            float4 v1 = *(const float4*)(src + 4);
            __half h8[8];
            h8[0] = __float2half_rn(v0.x); h8[1] = __float2half_rn(v0.y);
            h8[2] = __float2half_rn(v0.z); h8[3] = __float2half_rn(v0.w);
            h8[4] = __float2half_rn(v1.x); h8[5] = __float2half_rn(v1.y);
            h8[6] = __float2half_rn(v1.z); h8[7] = __float2half_rn(v1.w);
            uint32_t off = (uint32_t)r * 128u + (uint32_t)((ch ^ (r & 7)) << 4);
            *(uint4*)((char*)dst + off) = *(uint4*)h8;
        }
    } else if (b < 1536) {
        // ---- B pack: tile (q,kt) = 128 rows(n'=g*32+r) x 64 cols, transposed ----
        int idx = b - 512;
        int kt = idx & 31, q = idx >> 5;
        __half* dstTile = g_Bpack + ((size_t)q * NKT + kt) * B_TILE_HALF;

        for (int g = 0; g < 4; ++g) {
            int width = (g < 3) ? 3072 : 1024;
            const float* Wx = (g < 3) ? W_ifo_x : W_b_x;
            const float* Wh = (g < 3) ? W_ifo_h : W_b_h;
            int cbase = ((g < 3) ? g * 1024 : 0) + q * 32;

            for (int i2 = tid; i2 < 64 * 32; i2 += 256) {
                int kk = i2 >> 5, c = i2 & 31;
                int k = kt * BK + kk;
                float v = (k < 1024) ? Wx[(size_t)k * width + cbase + c]
                                     : Wh[(size_t)(k - 1024) * width + cbase + c];
                ts[kk * 33 + c] = v;
            }
            __syncthreads();

            {
                int r = tid >> 3, ch = tid & 7;
                if (r < 32) {
                    int np = g * 32 + r;
                    __half h8[8];
                    #pragma unroll
                    for (int u = 0; u < 8; ++u)
                        h8[u] = __float2half_rn(ts[(ch * 8 + u) * 33 + r]);
                    uint32_t off = (uint32_t)np * 128u + (uint32_t)((ch ^ (np & 7)) << 4);
                    *(uint4*)((char*)dstTile + off) = *(uint4*)h8;
                }
            }
            __syncthreads();
        }
    } else {
        // ---- bias ----
        int n = (b - 1536) * 256 + tid;        // n = q*128 + g*32 + j
        int q = n >> 7, g = (n >> 5) & 3, j = n & 31;
        int hid = q * 32 + j;
        float v;
        if (g < 3) v = b_ifo_x[g * 1024 + hid] + b_ifo_h[g * 1024 + hid];
        else       v = b_b_x[hid] + b_b_h[hid];
        g_bias[n] = v;
    }
}

// ============================================================================
// Main GEMM + fused LSTM epilogue
//   288 threads = 9 warps: warps 0-7 MMA (64x64, 4x2 over 256x128), warp 8 producer
// ============================================================================
__global__ void __launch_bounds__(288, 1)
lstm_gemm_kernel(const float* __restrict__ c_prev, float* __restrict__ out) {
    extern __shared__ char smem[];
    uint32_t smem_base = smem_u32(smem);
    int tid  = threadIdx.x;
    int lane = tid & 31;
    int wid  = tid >> 5;
    int mt = blockIdx.x;      // batch tile (256 rows)
    int q  = blockIdx.y;      // hid block

    uint32_t mbF = smem_base + SMO_MBAR;          // full barriers, 4 x 8B
    uint32_t mbE = smem_base + SMO_MBAR + 32;     // empty barriers, 4 x 8B
    if (tid == 0) {
        #pragma unroll
        for (int s = 0; s < NSTAGE; ++s) {
            MBARRIER_INIT(mbF + s * 8, 1);
            MBARRIER_INIT(mbE + s * 8, 8);        // one arrive per MMA warp
        }
    }
    __syncthreads();

    const __half* abase = g_Apack + (size_t)mt * NKT * A_TILE_HALF;
    const __half* bbase = g_Bpack + (size_t)q  * NKT * B_TILE_HALF;

    float acc[4][8][4];

    if (wid == 8) {
        // ---------------- producer warp ----------------
        if (lane == 0) {
            int s = 0, eph = 1;          // fresh-barrier trick: parity 1 passes
            for (int kt = 0; kt < NKT; ++kt) {
                MBARRIER_WAIT_PARITY(mbE + s * 8, eph);
                uint32_t sa = smem_base + SMO_STAGE + (uint32_t)s * STAGE_BYTES;
                MBARRIER_EXPECT_TX(mbF + s * 8, STAGE_BYTES);
                CP_BULK_G2S(sa, abase + (size_t)kt * A_TILE_HALF, A_TILE_BYTES, mbF + s * 8);
                CP_BULK_G2S(sa + A_TILE_BYTES, bbase + (size_t)kt * B_TILE_HALF,
                            B_TILE_BYTES, mbF + s * 8);
                if (++s == NSTAGE) { s = 0; eph ^= 1; }
            }
        }
    } else {
        // ---------------- MMA warps ----------------
        int wm = wid & 3;     // 4 warps over M (64 rows each of 256)
        int wn = wid >> 2;    // 2 warps over N (64 cols each of 128)

        uint32_t aRowOff[4], bRowOff[4];
        #pragma unroll
        for (int mi = 0; mi < 4; ++mi)
            aRowOff[mi] = (uint32_t)(wm * 64 + mi * 16 + ((lane >> 3) & 1) * 8 + (lane & 7)) * 128u;
        #pragma unroll
        for (int ni = 0; ni < 4; ++ni)
            bRowOff[ni] = (uint32_t)(wn * 64 + ni * 16 + ((lane >> 4) & 1) * 8 + (lane & 7)) * 128u
                          + (uint32_t)A_TILE_BYTES;
        int aChAdd = lane >> 4;          // 0/1
        int bChAdd = (lane >> 3) & 1;    // 0/1
        int lxor   = lane & 7;

        #pragma unroll
        for (int mi = 0; mi < 4; ++mi)
            #pragma unroll
            for (int nj = 0; nj < 8; ++nj)
                #pragma unroll
                for (int e = 0; e < 4; ++e) acc[mi][nj][e] = 0.0f;

        uint32_t af[4][4];        // A frags, rotated in place (mi-major order)
        uint32_t bf[2][4][4];     // B frags, double buffered

        int s = 0, fph = 0;
        for (int kt = 0; kt < NKT; ++kt) {
            MBARRIER_WAIT_PARITY(mbF + s * 8, fph);
            uint32_t st = smem_base + SMO_STAGE + (uint32_t)s * STAGE_BYTES;

            // kp = 0 loads (exposed once per k-tile)
            {
                uint32_t ca = (uint32_t)((aChAdd ^ lxor) << 4);
                uint32_t cb = (uint32_t)((bChAdd ^ lxor) << 4);
                #pragma unroll
                for (int ni = 0; ni < 4; ++ni)
                    LDMATRIX_X4(bf[0][ni][0], bf[0][ni][1], bf[0][ni][2], bf[0][ni][3],
                                st + bRowOff[ni] + cb);
                #pragma unroll
                for (int mi = 0; mi < 4; ++mi)
                    LDMATRIX_X4(af[mi][0], af[mi][1], af[mi][2], af[mi][3],
                                st + aRowOff[mi] + ca);
            }

            #pragma unroll
            for (int kp = 0; kp < 4; ++kp) {
                int cur = kp & 1;
                if (kp < 3) {
                    uint32_t cbn = (uint32_t)((((kp + 1) * 2 + bChAdd) ^ lxor) << 4);
                    #pragma unroll
                    for (int ni = 0; ni < 4; ++ni)
                        LDMATRIX_X4(bf[cur ^ 1][ni][0], bf[cur ^ 1][ni][1],
                                    bf[cur ^ 1][ni][2], bf[cur ^ 1][ni][3],
                                    st + bRowOff[ni] + cbn);
                }
                uint32_t can = (uint32_t)((((kp + 1) * 2 + aChAdd) ^ lxor) << 4);
                #pragma unroll
                for (int mi = 0; mi < 4; ++mi) {
                    #pragma unroll
                    for (int nj = 0; nj < 8; ++nj)
                        mma_fp16(acc[mi][nj], af[mi], &bf[cur][nj >> 1][(nj & 1) * 2]);
                    if (kp < 3)
                        LDMATRIX_X4(af[mi][0], af[mi][1], af[mi][2], af[mi][3],
                                    st + aRowOff[mi] + can);
                }
            }

            __syncwarp();
            if (lane == 0) MBARRIER_ARRIVE(mbE + s * 8);
            if (++s == NSTAGE) { s = 0; fph ^= 1; }
        }
    }

    // ---- fused LSTM epilogue (reuse stage smem) ----
    __syncthreads();                                  // all warps past mainloop
    float* gs     = (float*)(smem + SMO_STAGE);       // [256][132]
    float* bias_s = (float*)(smem + SMO_STAGE + 256 * GS_STRIDE * 4);
    if (tid < 128) bias_s[tid] = g_bias[q * 128 + tid];

    if (wid < 8) {
        int wm = wid & 3;
        int wn = wid >> 2;
        #pragma unroll
        for (int mi = 0; mi < 4; ++mi) {
            #pragma unroll
            for (int nj = 0; nj < 8; ++nj) {
                int r   = wm * 64 + mi * 16 + (lane >> 2);
                int col = wn * 64 + nj * 8 + (lane & 3) * 2;
                gs[r * GS_STRIDE + col]           = acc[mi][nj][0];
                gs[r * GS_STRIDE + col + 1]       = acc[mi][nj][1];
                gs[(r + 8) * GS_STRIDE + col]     = acc[mi][nj][2];
                gs[(r + 8) * GS_STRIDE + col + 1] = acc[mi][nj][3];
            }
        }
    }
    __syncthreads();

    int m0 = mt * BM;
    if (wid < 8) {
        for (int rr = wid; rr < 256; rr += 8) {
            float gi = gs[rr * GS_STRIDE +  0 + lane] + bias_s[ 0 + lane];
            float gf = gs[rr * GS_STRIDE + 32 + lane] + bias_s[32 + lane];
            float go = gs[rr * GS_STRIDE + 64 + lane] + bias_s[64 + lane];
            float ga = gs[rr * GS_STRIDE + 96 + lane] + bias_s[96 + lane];
            size_t o = (size_t)(m0 + rr) * 1024 + q * 32 + lane;
            float cp = c_prev[o];
            float iv = fast_sigmoid(gi);
            float fv = fast_sigmoid(gf);
            float ov = fast_sigmoid(go);
            float av = fast_tanh(ga);
            float cn = fmaf(fv, cp, iv * av);
            float hn = ov * fast_tanh(cn);
            out[o] = hn;
            out[(size_t)BATCH * 1024 + o] = cn;
        }
    }
}

// ============================================================================
// kernel_launch
// ============================================================================
extern "C" void kernel_launch(void* const* d_in, const int* in_sizes, int n_in,
                              void* d_out, int out_size) {
    const float* x       = (const float*)d_in[0];
    const float* h_prev  = (const float*)d_in[1];
    const float* c_prev  = (const float*)d_in[2];
    const float* W_ifo_x = (const float*)d_in[3];
    const float* b_ifo_x = (const float*)d_in[4];
    const float* W_ifo_h = (const float*)d_in[5];
    const float* b_ifo_h = (const float*)d_in[6];
    const float* W_b_x   = (const float*)d_in[7];
    const float* b_b_x   = (const float*)d_in[8];
    const float* W_b_h   = (const float*)d_in[9];
    const float* b_b_h   = (const float*)d_in[10];
    float* out = (float*)d_out;
    (void)in_sizes; (void)n_in; (void)out_size;

    cudaFuncSetAttribute(lstm_gemm_kernel,
                         cudaFuncAttributeMaxDynamicSharedMemorySize, SMEM_TOTAL);

    prep_all_kernel<<<1552, 256>>>(x, h_prev, W_ifo_x, W_ifo_h, W_b_x, W_b_h,
                                   b_ifo_x, b_ifo_h, b_b_x, b_b_h);
    lstm_gemm_kernel<<<dim3(MT, NQ), 288, SMEM_TOTAL>>>(c_prev, out);
}

// round 14
// speedup vs baseline: 1.2765x; 1.2765x over previous
#include <cuda_runtime.h>
#include <cuda_fp16.h>
#include <cstdint>

// ============================================================================
// GlobalLSTMCell: h,c = LSTM(x, h_prev, c_prev; W_ifo, W_b)
//   GEMM view: A = [x | h_prev]  (4096 x 2048)
//              Bp[n',k], n' = q*128 + gate*32 + j, hid = q*32 + j, gate in {i,f,o,a}
//   D = A @ Bp^T  (4096 x 4096), then fused pointwise LSTM epilogue.
//
// R14 = R7 (best: 2 CTAs/SM, dedicated producer warp, 3-stage, B-frag double
// buffer + A-frag rotation) + EARLY EMPTY-ARRIVE: signal stage-free before the
// last (SMEM-free) MMA batch of each k-tile, giving the producer a head start.
// ============================================================================

#define BATCH 4096
#define KDIM  2048
#define HID   1024

#define BM 128
#define BN 128
#define BK 64
#define NKT (KDIM / BK)     // 32 k-tiles
#define MT  (BATCH / BM)    // 32
#define NQ  (HID / 32)      // 32 q-blocks

#define A_TILE_HALF (BM * BK)   // 8192 halves = 16 KB
#define B_TILE_HALF (BN * BK)   // 8192 halves = 16 KB
#define STAGE_BYTES 32768       // A tile + B tile
#define NSTAGE 3

// Scratch (__device__ globals only — no allocation allowed)
__device__ __half g_Apack[(size_t)MT * NKT * A_TILE_HALF];   // 16 MB
__device__ __half g_Bpack[(size_t)NQ * NKT * B_TILE_HALF];   // 16 MB
__device__ float  g_bias[4096];

// ============================================================================
// PTX helpers (base-target features only)
// ============================================================================
__device__ __forceinline__ uint32_t smem_u32(const void* p) {
    uint32_t a;
    asm("{ .reg .u64 t; cvta.to.shared.u64 t, %1; cvt.u32.u64 %0, t; }" : "=r"(a) : "l"(p));
    return a;
}

#define MBARRIER_INIT(addr, cnt) \
    asm volatile("mbarrier.init.shared.b64 [%0], %1;" :: "r"(addr), "r"((uint32_t)(cnt)) : "memory")

#define MBARRIER_EXPECT_TX(addr, tx) \
    asm volatile("mbarrier.arrive.expect_tx.shared.b64 _, [%0], %1;" \
                 :: "r"(addr), "r"((uint32_t)(tx)) : "memory")

#define MBARRIER_ARRIVE(addr) \
    asm volatile("mbarrier.arrive.shared.b64 _, [%0];" :: "r"(addr) : "memory")

#define MBARRIER_WAIT_PARITY(mbar_smem_addr, phase_parity) do {                        \
    uint32_t _mbar = (uint32_t)(mbar_smem_addr);                                       \
    uint32_t _parity = (uint32_t)(phase_parity);                                       \
    uint32_t _done;                                                                    \
    asm volatile("{ .reg .pred p;"                                                     \
        " mbarrier.try_wait.parity.acquire.cta.shared::cta.b64 p, [%1], %2;"           \
        " selp.b32 %0, 1, 0, p; }"                                                     \
        : "=r"(_done) : "r"(_mbar), "r"(_parity) : "memory");                          \
    if (!_done) {                                                                      \
        asm volatile("{ .reg .pred P1;"                                                \
            " WAIT_LOOP_%=:"                                                           \
            " mbarrier.try_wait.parity.acquire.cta.shared::cta.b64 P1, [%0], %1, 0x989680;" \
            " @P1 bra.uni WAIT_DONE_%=;"                                               \
            " bra.uni WAIT_LOOP_%=;"                                                   \
            " WAIT_DONE_%=: }"                                                         \
            :: "r"(_mbar), "r"(_parity) : "memory");                                   \
    }                                                                                  \
} while (0)

// 1D bulk async copy gmem -> smem with mbarrier tx completion (sm_90 base).
#define CP_BULK_G2S(dst_u32, src_ptr, bytes, mbar_u32) \
    asm volatile("cp.async.bulk.shared::cluster.global.mbarrier::complete_tx::bytes " \
                 "[%0], [%1], %2, [%3];" \
                 :: "r"(dst_u32), "l"(src_ptr), "r"((uint32_t)(bytes)), "r"(mbar_u32) : "memory")

#define LDMATRIX_X4(r0, r1, r2, r3, addr) \
    asm volatile("ldmatrix.sync.aligned.m8n8.x4.shared.b16 {%0,%1,%2,%3}, [%4];" \
                 : "=r"(r0), "=r"(r1), "=r"(r2), "=r"(r3) : "r"(addr))

__device__ __forceinline__ void mma_fp16(float* c, const uint32_t* a, const uint32_t* b) {
    asm volatile("mma.sync.aligned.m16n8k16.row.col.f32.f16.f16.f32 "
                 "{%0,%1,%2,%3}, {%4,%5,%6,%7}, {%8,%9}, {%0,%1,%2,%3};"
                 : "+f"(c[0]), "+f"(c[1]), "+f"(c[2]), "+f"(c[3])
                 : "r"(a[0]), "r"(a[1]), "r"(a[2]), "r"(a[3]), "r"(b[0]), "r"(b[1]));
}

__device__ __forceinline__ float fast_sigmoid(float x) {
    return 1.0f / (1.0f + __expf(-x));
}
__device__ __forceinline__ float fast_tanh(float x) {
    float xc = fminf(fmaxf(x, -15.0f), 15.0f);
    float e2 = __expf(2.0f * xc);
    return (e2 - 1.0f) / (e2 + 1.0f);
}

// ============================================================================
// SMEM layout (dynamic): [0..48) mbarriers (3 full + 3 empty), stages at 1024.
// Epilogue reuses stage area: gate tile fp32 [128][132] + bias[128].
// ============================================================================
#define SMO_MBAR   0
#define SMO_STAGE  1024
#define SMEM_TOTAL (SMO_STAGE + NSTAGE * STAGE_BYTES)   // 99328 -> 2 CTAs/SM
#define GS_STRIDE  132

// ============================================================================
// Prep kernels: pack fp16 + pre-swizzle (SW128: chunk' = chunk ^ (row&7))
// ============================================================================
__global__ void prep_bias_kernel(const float* __restrict__ b_ifo_x, const float* __restrict__ b_ifo_h,
                                 const float* __restrict__ b_b_x,  const float* __restrict__ b_b_h) {
    int n = blockIdx.x * 256 + threadIdx.x;     // n = q*128 + g*32 + j
    int q = n >> 7, g = (n >> 5) & 3, j = n & 31;
    int hid = q * 32 + j;
    float v;
    if (g < 3) v = b_ifo_x[g * 1024 + hid] + b_ifo_h[g * 1024 + hid];
    else       v = b_b_x[hid] + b_b_h[hid];
    g_bias[n] = v;
}

// A pack: tile (mt,kt) = 128 rows(m) x 64 cols(k) fp16, 128B rows, swizzled chunks.
__global__ void prep_a_kernel(const float* __restrict__ x, const float* __restrict__ h_prev) {
    int kt = blockIdx.x, mt = blockIdx.y;
    __half* dst = g_Apack + ((size_t)mt * NKT + kt) * A_TILE_HALF;
    for (int task = threadIdx.x; task < 128 * 8; task += 256) {
        int r = task >> 3, ch = task & 7;             // row, 16B chunk (8 halves)
        int m = mt * BM + r;
        int k0 = kt * BK + ch * 8;
        const float* src = (k0 < 1024) ? (x + (size_t)m * 1024 + k0)
                                       : (h_prev + (size_t)m * 1024 + (k0 - 1024));
        float4 v0 = *(const float4*)(src);
        float4 v1 = *(const float4*)(src + 4);
        __half h8[8];
        h8[0] = __float2half_rn(v0.x); h8[1] = __float2half_rn(v0.y);
        h8[2] = __float2half_rn(v0.z); h8[3] = __float2half_rn(v0.w);
        h8[4] = __float2half_rn(v1.x); h8[5] = __float2half_rn(v1.y);
        h8[6] = __float2half_rn(v1.z); h8[7] = __float2half_rn(v1.w);
        uint32_t off = (uint32_t)r * 128u + (uint32_t)((ch ^ (r & 7)) << 4);
        *(uint4*)((char*)dst + off) = *(uint4*)h8;
    }
}

// B pack: tile (q,kt) = 128 rows(n' = g*32+r) x 64 cols(k), transposed from W via smem.
__global__ void prep_b_kernel(const float* __restrict__ W_ifo_x, const float* __restrict__ W_ifo_h,
                              const float* __restrict__ W_b_x,  const float* __restrict__ W_b_h) {
    __shared__ float ts[64 * 33];
    int kt = blockIdx.x, q = blockIdx.y;
    __half* dstTile = g_Bpack + ((size_t)q * NKT + kt) * B_TILE_HALF;
    int tid = threadIdx.x;

    for (int g = 0; g < 4; ++g) {
        int width = (g < 3) ? 3072 : 1024;
        const float* Wx = (g < 3) ? W_ifo_x : W_b_x;
        const float* Wh = (g < 3) ? W_ifo_h : W_b_h;
        int cbase = ((g < 3) ? g * 1024 : 0) + q * 32;

        // Load 64(k) x 32(col) coalesced into smem (transposed access later).
        for (int idx = tid; idx < 64 * 32; idx += 256) {
            int kk = idx >> 5, c = idx & 31;
            int k = kt * BK + kk;
            float v = (k < 1024) ? Wx[(size_t)k * width + cbase + c]
                                 : Wh[(size_t)(k - 1024) * width + cbase + c];
            ts[kk * 33 + c] = v;
        }
        __syncthreads();

        // Write rows n' = g*32 + r, 8 k-contiguous halves per 16B chunk, swizzled.
        {
            int r = tid >> 3, ch = tid & 7;           // 256 tasks exactly
            if (r < 32) {
                int np = g * 32 + r;
                __half h8[8];
                #pragma unroll
                for (int u = 0; u < 8; ++u)
                    h8[u] = __float2half_rn(ts[(ch * 8 + u) * 33 + r]);
                uint32_t off = (uint32_t)np * 128u + (uint32_t)((ch ^ (np & 7)) << 4);
                *(uint4*)((char*)dstTile + off) = *(uint4*)h8;
            }
        }
        __syncthreads();
    }
}

// ============================================================================
// Main GEMM + fused LSTM epilogue
//   160 threads = 5 warps: warps 0-3 MMA (64x64 tiles), warp 4 = producer.
// ============================================================================
__global__ void __launch_bounds__(160, 2)
lstm_gemm_kernel(const float* __restrict__ c_prev, float* __restrict__ out) {
    extern __shared__ char smem[];
    uint32_t smem_base = smem_u32(smem);
    int tid  = threadIdx.x;
    int lane = tid & 31;
    int wid  = tid >> 5;
    int mt = blockIdx.x;      // batch tile
    int q  = blockIdx.y;      // hid block

    uint32_t mbF = smem_base + SMO_MBAR;          // full barriers, 3 x 8B
    uint32_t mbE = smem_base + SMO_MBAR + 24;     // empty barriers, 3 x 8B
    if (tid == 0) {
        #pragma unroll
        for (int s = 0; s < NSTAGE; ++s) {
            MBARRIER_INIT(mbF + s * 8, 1);
            MBARRIER_INIT(mbE + s * 8, 4);        // one arrive per MMA warp
        }
    }
    __syncthreads();

    const __half* abase = g_Apack + (size_t)mt * NKT * A_TILE_HALF;
    const __half* bbase = g_Bpack + (size_t)q  * NKT * B_TILE_HALF;

    float acc[4][8][4];

    if (wid == 4) {
        // ---------------- producer warp ----------------
        if (lane == 0) {
            int s = 0, eph = 1;          // fresh-barrier trick: parity 1 passes
            for (int kt = 0; kt < NKT; ++kt) {
                MBARRIER_WAIT_PARITY(mbE + s * 8, eph);
                uint32_t sa = smem_base + SMO_STAGE + (uint32_t)s * STAGE_BYTES;
                MBARRIER_EXPECT_TX(mbF + s * 8, STAGE_BYTES);
                CP_BULK_G2S(sa,         abase + (size_t)kt * A_TILE_HALF, 16384, mbF + s * 8);
                CP_BULK_G2S(sa + 16384, bbase + (size_t)kt * B_TILE_HALF, 16384, mbF + s * 8);
                if (++s == NSTAGE) { s = 0; eph ^= 1; }
            }
        }
    } else {
        // ---------------- MMA warps ----------------
        int wm = wid & 1;     // 2 warps over M (64 rows each)
        int wn = wid >> 1;    // 2 warps over N (64 cols each)

        uint32_t aRowOff[4], bRowOff[4];
        #pragma unroll
        for (int mi = 0; mi < 4; ++mi)
            aRowOff[mi] = (uint32_t)(wm * 64 + mi * 16 + ((lane >> 3) & 1) * 8 + (lane & 7)) * 128u;
        #pragma unroll
        for (int ni = 0; ni < 4; ++ni)
            bRowOff[ni] = (uint32_t)(wn * 64 + ni * 16 + ((lane >> 4) & 1) * 8 + (lane & 7)) * 128u
                          + 16384u;
        int aChAdd = lane >> 4;          // 0/1
        int bChAdd = (lane >> 3) & 1;    // 0/1
        int lxor   = lane & 7;

        #pragma unroll
        for (int mi = 0; mi < 4; ++mi)
            #pragma unroll
            for (int nj = 0; nj < 8; ++nj)
                #pragma unroll
                for (int e = 0; e < 4; ++e) acc[mi][nj][e] = 0.0f;

        uint32_t af[4][4];        // A frags, rotated in place (mi-major order)
        uint32_t bf[2][4][4];     // B frags, double buffered

        int s = 0, fph = 0;
        for (int kt = 0; kt < NKT; ++kt) {
            MBARRIER_WAIT_PARITY(mbF + s * 8, fph);
            uint32_t st = smem_base + SMO_STAGE + (uint32_t)s * STAGE_BYTES;

            // kp = 0 loads (exposed once per k-tile)
            {
                uint32_t ca = (uint32_t)((aChAdd ^ lxor) << 4);
                uint32_t cb = (uint32_t)((bChAdd ^ lxor) << 4);
                #pragma unroll
                for (int ni = 0; ni < 4; ++ni)
                    LDMATRIX_X4(bf[0][ni][0], bf[0][ni][1], bf[0][ni][2], bf[0][ni][3],
                                st + bRowOff[ni] + cb);
                #pragma unroll
                for (int mi = 0; mi < 4; ++mi)
                    LDMATRIX_X4(af[mi][0], af[mi][1], af[mi][2], af[mi][3],
                                st + aRowOff[mi] + ca);
            }

            // kp = 0..2: prefetch next kp's frags, rotate A in place (mi-major)
            #pragma unroll
            for (int kp = 0; kp < 3; ++kp) {
                int cur = kp & 1;
                uint32_t cbn = (uint32_t)((((kp + 1) * 2 + bChAdd) ^ lxor) << 4);
                #pragma unroll
                for (int ni = 0; ni < 4; ++ni)
                    LDMATRIX_X4(bf[cur ^ 1][ni][0], bf[cur ^ 1][ni][1],
                                bf[cur ^ 1][ni][2], bf[cur ^ 1][ni][3],
                                st + bRowOff[ni] + cbn);
                uint32_t can = (uint32_t)((((kp + 1) * 2 + aChAdd) ^ lxor) << 4);
                #pragma unroll
                for (int mi = 0; mi < 4; ++mi) {
                    #pragma unroll
                    for (int nj = 0; nj < 8; ++nj)
                        mma_fp16(acc[mi][nj], af[mi], &bf[cur][nj >> 1][(nj & 1) * 2]);
                    LDMATRIX_X4(af[mi][0], af[mi][1], af[mi][2], af[mi][3],
                                st + aRowOff[mi] + can);
                }
            }

            // EARLY ARRIVE: all SMEM reads of stage s are issued (kp=3 frags are
            // in registers) -> free the stage before the last MMA batch.
            __syncwarp();
            if (lane == 0) MBARRIER_ARRIVE(mbE + s * 8);

            // kp = 3: MMA only, no SMEM access
            #pragma unroll
            for (int mi = 0; mi < 4; ++mi)
                #pragma unroll
                for (int nj = 0; nj < 8; ++nj)
                    mma_fp16(acc[mi][nj], af[mi], &bf[1][nj >> 1][(nj & 1) * 2]);

            if (++s == NSTAGE) { s = 0; fph ^= 1; }
        }
    }

    // ---- fused LSTM epilogue (reuse stage smem) ----
    __syncthreads();                                  // all warps past mainloop
    float* gs     = (float*)(smem + SMO_STAGE);       // [128][132]
    float* bias_s = (float*)(smem + SMO_STAGE + 128 * GS_STRIDE * 4);
    if (tid < 128) bias_s[tid] = g_bias[q * 128 + tid];

    if (wid < 4) {
        int wm = wid & 1;
        int wn = wid >> 1;
        #pragma unroll
        for (int mi = 0; mi < 4; ++mi) {
            #pragma unroll
            for (int nj = 0; nj < 8; ++nj) {
                int r   = wm * 64 + mi * 16 + (lane >> 2);
                int col = wn * 64 + nj * 8 + (lane & 3) * 2;
                gs[r * GS_STRIDE + col]           = acc[mi][nj][0];
                gs[r * GS_STRIDE + col + 1]       = acc[mi][nj][1];
                gs[(r + 8) * GS_STRIDE + col]     = acc[mi][nj][2];
                gs[(r + 8) * GS_STRIDE + col + 1] = acc[mi][nj][3];
            }
        }
    }
    __syncthreads();

    int m0 = mt * BM;
    for (int rr = wid; rr < 128; rr += 5) {
        float gi = gs[rr * GS_STRIDE +  0 + lane] + bias_s[ 0 + lane];
        float gf = gs[rr * GS_STRIDE + 32 + lane] + bias_s[32 + lane];
        float go = gs[rr * GS_STRIDE + 64 + lane] + bias_s[64 + lane];
        float ga = gs[rr * GS_STRIDE + 96 + lane] + bias_s[96 + lane];
        size_t o = (size_t)(m0 + rr) * 1024 + q * 32 + lane;
        float cp = c_prev[o];
        float iv = fast_sigmoid(gi);
        float fv = fast_sigmoid(gf);
        float ov = fast_sigmoid(go);
        float av = fast_tanh(ga);
        float cn = fmaf(fv, cp, iv * av);
        float hn = ov * fast_tanh(cn);
        out[o] = hn;
        out[(size_t)BATCH * 1024 + o] = cn;
    }
}

// ============================================================================
// kernel_launch
// ============================================================================
extern "C" void kernel_launch(void* const* d_in, const int* in_sizes, int n_in,
                              void* d_out, int out_size) {
    const float* x       = (const float*)d_in[0];
    const float* h_prev  = (const float*)d_in[1];
    const float* c_prev  = (const float*)d_in[2];
    const float* W_ifo_x = (const float*)d_in[3];
    const float* b_ifo_x = (const float*)d_in[4];
    const float* W_ifo_h = (const float*)d_in[5];
    const float* b_ifo_h = (const float*)d_in[6];
    const float* W_b_x   = (const float*)d_in[7];
    const float* b_b_x   = (const float*)d_in[8];
    const float* W_b_h   = (const float*)d_in[9];
    const float* b_b_h   = (const float*)d_in[10];
    float* out = (float*)d_out;
    (void)in_sizes; (void)n_in; (void)out_size;

    cudaFuncSetAttribute(lstm_gemm_kernel,
                         cudaFuncAttributeMaxDynamicSharedMemorySize, SMEM_TOTAL);

    prep_bias_kernel<<<16, 256>>>(b_ifo_x, b_ifo_h, b_b_x, b_b_h);
    prep_a_kernel<<<dim3(NKT, MT), 256>>>(x, h_prev);
    prep_b_kernel<<<dim3(NKT, NQ), 256>>>(W_ifo_x, W_ifo_h, W_b_x, W_b_h);
    lstm_gemm_kernel<<<dim3(MT, NQ), 160, SMEM_TOTAL>>>(c_prev, out);
}